// round 13
// baseline (speedup 1.0000x reference)
#include <cuda_runtime.h>
#include <cuda_fp16.h>
#include <cstdint>

#define N_NODES 4096
#define N_EDGES 65536
#define LDIM 64
#define KDIM 256
#define EDIM 6
#define KL (KDIM*LDIM)   /* 16384 */
#define MAXDEG 128       /* bucket capacity; Poisson(16) => P(deg>128) ~ 0 */
#define SLICE_N 2048     /* nodes per P slice: 64 MB fp16, L2-resident */

// Layout note: g_P and g_h use a PERMUTED k-order (warp-tile-relative
// tg*8+ni*2+half), identical in both producers; k_edge contracts
// position-by-position so the dot over k is unchanged. o is NOT permuted.
// g_P holds ONE slice (SLICE_N nodes) at a time, reused across slices/convs.

// ---------------- scratch (device globals; no runtime allocation) ----------------
__device__ __half g_W3pT[(size_t)KL*LDIM];        // [col=o*256+k][i]  fp16, 2 MB
__device__ __half g_W2T[KDIM*KDIM];               // [n][k] fp16
__device__ __half g_xh[N_NODES*LDIM];             // fp16 copy of current x
__device__ __half g_h [(size_t)N_EDGES*KDIM];     // 32 MB fp16 (permuted k)
__device__ __half g_P [(size_t)SLICE_N*KL];       // 64 MB fp16 slice, [nl][o][permuted k]
__device__ float  g_x1 [N_NODES*LDIM];
__device__ float  g_xb3[N_NODES*LDIM];
__device__ float  g_agg [N_NODES*LDIM];
__device__ float  g_agg2[N_NODES*LDIM];
__device__ int    g_deg[N_NODES];
__device__ int    g_csr[N_NODES*MAXDEG];          // bucketed edge ids (2 MB)

// ---------------- helpers ----------------
__device__ __forceinline__ float gelu_f(float x){
    return 0.5f * x * (1.0f + erff(x * 0.70710678118654752440f));
}
__device__ __forceinline__ void mma16(float* c, const uint32_t* a, const uint32_t* b){
    asm volatile(
        "mma.sync.aligned.m16n8k16.row.col.f32.f16.f16.f32 "
        "{%0,%1,%2,%3}, {%4,%5,%6,%7}, {%8,%9}, {%0,%1,%2,%3};\n"
        : "+f"(c[0]), "+f"(c[1]), "+f"(c[2]), "+f"(c[3])
        : "r"(a[0]), "r"(a[1]), "r"(a[2]), "r"(a[3]), "r"(b[0]), "r"(b[1]));
}
__device__ __forceinline__ uint32_t smaddr(const void* p){
    return (uint32_t)__cvta_generic_to_shared(p);
}
__device__ __forceinline__ void ldsm_x4(uint32_t* r, uint32_t a){
    asm volatile("ldmatrix.sync.aligned.m8n8.x4.shared.b16 {%0,%1,%2,%3}, [%4];"
        : "=r"(r[0]), "=r"(r[1]), "=r"(r[2]), "=r"(r[3]) : "r"(a));
}
__device__ __forceinline__ void ldsm_x2(uint32_t* r, uint32_t a){
    asm volatile("ldmatrix.sync.aligned.m8n8.x2.shared.b16 {%0,%1}, [%2];"
        : "=r"(r[0]), "=r"(r[1]) : "r"(a));
}
__device__ __forceinline__ void cp16(void* smem_dst, const void* gsrc){
    asm volatile("cp.async.cg.shared.global [%0], [%1], 16;\n"
                 :: "r"(smaddr(smem_dst)), "l"(gsrc));
}
__device__ __forceinline__ void cp_commit(){
    asm volatile("cp.async.commit_group;\n");
}
template<int N> __device__ __forceinline__ void cp_wait(){
    asm volatile("cp.async.wait_group %0;\n" :: "n"(N));
}

// ---------------- fused prep: W3/W2 fp16 transposes, x->fp16, xb3, zero agg/deg ----------------
__global__ void k_prep(const float* __restrict__ W3, const float* __restrict__ W2,
                       const float* __restrict__ nodes, const float* __restrict__ b3){
    int idx = blockIdx.x*256 + threadIdx.x;        // 0 .. 1048575
    {   // W3pT[(o*256+k)*64 + i] = W3[k, i*64+o]
        int col = idx >> 6, i = idx & 63;
        int o = col >> 8, k = col & 255;
        g_W3pT[idx] = __float2half_rn(W3[k*(LDIM*LDIM) + i*LDIM + o]);
    }
    if (idx < KDIM*KDIM){
        int n = idx >> 8, k = idx & 255;
        g_W2T[idx] = __float2half_rn(W2[k*KDIM + n]);
    }
    if (idx < N_NODES*LDIM){
        g_agg[idx]  = 0.f;
        g_agg2[idx] = 0.f;
        g_xh[idx]   = __float2half_rn(nodes[idx]);
        int n = idx >> 6, o = idx & 63;
        const float* xr = nodes + n*LDIM;
        float v = 0.f;
        #pragma unroll 8
        for (int i = 0; i < LDIM; i++) v += xr[i] * __ldg(&b3[i*LDIM + o]);
        g_xb3[idx] = v;
    }
    if (idx < N_NODES) g_deg[idx] = 0;
}

// ---------------- fp16 GEMM for P slice: cp.async staging, permuted coalesced epilogue ----------------
#define BMt 128
#define BNt 128
#define PAST 72

__global__ __launch_bounds__(256, 3) void k_gemmP(
    const __half* __restrict__ A, __half* __restrict__ C, int n0base)
{
    __shared__ __half As[BMt*PAST];
    __shared__ __half Bs[BNt*PAST];
    const int N = KL, K = LDIM;
    int tid = threadIdx.x;
    int lane = tid & 31, warp = tid >> 5;
    int g = lane >> 2, tg = lane & 3;
    int wm = (warp >> 2) * 64;
    int wn = (warp & 3) * 32;
    size_t bmL = (size_t)blockIdx.y * BMt;           // local (slice) row
    size_t bmG = (size_t)n0base + bmL;               // global node row
    size_t bn0 = (size_t)blockIdx.x * BNt;

    #pragma unroll
    for (int i = tid; i < BMt*8; i += 256){
        int r = i >> 3, s = (i & 7) << 3;
        cp16(&As[r*PAST + s], A + (bmG + r)*K + s);
    }
    #pragma unroll
    for (int i = tid; i < BNt*8; i += 256){
        int r = i >> 3, s = (i & 7) << 3;
        cp16(&Bs[r*PAST + s], g_W3pT + (size_t)(bn0 + r)*K + s);
    }
    cp_commit();

    float acc[4][4][4];
    #pragma unroll
    for (int a=0;a<4;a++)
        #pragma unroll
        for (int b=0;b<4;b++)
            #pragma unroll
            for (int c=0;c<4;c++) acc[a][b][c] = 0.f;

    int ra = (lane & 7) + ((lane >> 3) & 1) * 8;
    int ca = ((lane >> 4) & 1) * 8;
    int rb = (lane & 7) + ((lane >> 4) & 1) * 8;
    int cb = ((lane >> 3) & 1) * 8;

    cp_wait<0>();
    __syncthreads();

    #pragma unroll
    for (int kk = 0; kk < K; kk += 16){
        uint32_t af[4][4], bf[4][2];
        #pragma unroll
        for (int mi=0; mi<4; mi++)
            ldsm_x4(af[mi], smaddr(&As[(wm + mi*16 + ra)*PAST + kk + ca]));
        #pragma unroll
        for (int p=0; p<2; p++){
            uint32_t r4[4];
            ldsm_x4(r4, smaddr(&Bs[(wn + p*16 + rb)*PAST + kk + cb]));
            bf[2*p  ][0] = r4[0]; bf[2*p  ][1] = r4[1];
            bf[2*p+1][0] = r4[2]; bf[2*p+1][1] = r4[3];
        }
        #pragma unroll
        for (int mi=0; mi<4; mi++)
            #pragma unroll
            for (int ni=0; ni<4; ni++)
                mma16(acc[mi][ni], af[mi], bf[ni]);
    }

    size_t cbase = bn0 + wn + tg*8;
    #pragma unroll
    for (int mi=0; mi<4; mi++){
        size_t r0 = bmL + wm + mi*16 + g;            // local row into slice buffer
        uint4 v0, v1;
        __half2* p0 = (__half2*)&v0;
        __half2* p1 = (__half2*)&v1;
        #pragma unroll
        for (int ni=0; ni<4; ni++){
            p0[ni] = __floats2half2_rn(acc[mi][ni][0], acc[mi][ni][1]);
            p1[ni] = __floats2half2_rn(acc[mi][ni][2], acc[mi][ni][3]);
        }
        *(uint4*)(C + r0*N + cbase)     = v0;
        *(uint4*)(C + (r0+8)*N + cbase) = v1;
    }
}

// ---------------- fused h GEMM (fp16) + edge bucketing prologue ----------------
#define HAST 40
#define HBKT 32

__global__ __launch_bounds__(256) void k_hgemm(
    const float* __restrict__ ea, const float* __restrict__ W1, const float* __restrict__ b1,
    const float* __restrict__ b2, const int* __restrict__ ei)
{
    __shared__ __half As[BMt*HAST];
    __shared__ __half Bs[BMt*HAST];
    __shared__ float eas[BMt*EDIM];
    __shared__ float W1s[EDIM*KDIM];
    __shared__ float b1s[KDIM];
    int tid = threadIdx.x;

    // ---- bucket CSR build: 1024 blocks x 256 threads >= 65536 edges ----
    {
        int gtid = (blockIdx.y * gridDim.x + blockIdx.x) * 256 + tid;
        if (gtid < N_EDGES){
            int s = ei[gtid];
            int slot = atomicAdd(&g_deg[s], 1);
            g_csr[s*MAXDEG + slot] = gtid;
        }
    }

    int lane = tid & 31, warp = tid >> 5;
    int g = lane >> 2, tg = lane & 3;
    int wm = (warp >> 2) * 64;
    int wn = (warp & 3) * 32;
    size_t bm0 = (size_t)blockIdx.y * BMt;
    size_t bn0 = (size_t)blockIdx.x * BNt;

    for (int i = tid; i < BMt*EDIM; i += 256) eas[i] = ea[bm0*EDIM + i];
    for (int i = tid; i < EDIM*KDIM; i += 256) W1s[i] = W1[i];
    if (tid < KDIM) b1s[tid] = b1[tid];

    float acc[4][4][4];
    #pragma unroll
    for (int a=0;a<4;a++)
        #pragma unroll
        for (int b=0;b<4;b++)
            #pragma unroll
            for (int c=0;c<4;c++) acc[a][b][c] = 0.f;

    int ra = (lane & 7) + ((lane >> 3) & 1) * 8;
    int ca = ((lane >> 4) & 1) * 8;
    int rb = (lane & 7) + ((lane >> 4) & 1) * 8;
    int cb = ((lane >> 3) & 1) * 8;

    __syncthreads();

    for (int k0 = 0; k0 < KDIM; k0 += HBKT){
        #pragma unroll
        for (int i = tid; i < BMt*4; i += 256){
            int r = i >> 2, s = (i & 3) << 3;
            cp16(&Bs[r*HAST + s], g_W2T + (size_t)(bn0 + r)*KDIM + k0 + s);
        }
        cp_commit();
        {
            int c = tid & 31;
            int rg = tid >> 5;
            float w0 = W1s[0*KDIM + k0 + c], w1 = W1s[1*KDIM + k0 + c];
            float w2 = W1s[2*KDIM + k0 + c], w3 = W1s[3*KDIM + k0 + c];
            float w4 = W1s[4*KDIM + k0 + c], w5 = W1s[5*KDIM + k0 + c];
            float bb = b1s[k0 + c];
            #pragma unroll
            for (int i = 0; i < 16; i++){
                int r = rg*16 + i;
                const float* er = &eas[r*EDIM];
                float v = bb + er[0]*w0 + er[1]*w1 + er[2]*w2 + er[3]*w3 + er[4]*w4 + er[5]*w5;
                As[r*HAST + c] = __float2half_rn(gelu_f(v));
            }
        }
        cp_wait<0>();
        __syncthreads();
        #pragma unroll
        for (int kk = 0; kk < HBKT; kk += 16){
            uint32_t af[4][4], bf[4][2];
            #pragma unroll
            for (int mi=0; mi<4; mi++)
                ldsm_x4(af[mi], smaddr(&As[(wm + mi*16 + ra)*HAST + kk + ca]));
            #pragma unroll
            for (int p=0; p<2; p++){
                uint32_t r4[4];
                ldsm_x4(r4, smaddr(&Bs[(wn + p*16 + rb)*HAST + kk + cb]));
                bf[2*p  ][0] = r4[0]; bf[2*p  ][1] = r4[1];
                bf[2*p+1][0] = r4[2]; bf[2*p+1][1] = r4[3];
            }
            #pragma unroll
            for (int mi=0; mi<4; mi++)
                #pragma unroll
                for (int ni=0; ni<4; ni++)
                    mma16(acc[mi][ni], af[mi], bf[ni]);
        }
        __syncthreads();
    }

    size_t cbase = bn0 + wn + tg*8;
    #pragma unroll
    for (int mi=0; mi<4; mi++){
        size_t r0 = bm0 + wm + mi*16 + g;
        uint4 v0, v1;
        __half2* p0 = (__half2*)&v0;
        __half2* p1 = (__half2*)&v1;
        #pragma unroll
        for (int ni=0; ni<4; ni++){
            int cg = (int)bn0 + wn + ni*8 + (tg<<1);
            float bb0 = b2[cg], bb1 = b2[cg+1];
            p0[ni] = __floats2half2_rn(gelu_f(acc[mi][ni][0] + bb0), gelu_f(acc[mi][ni][1] + bb1));
            p1[ni] = __floats2half2_rn(gelu_f(acc[mi][ni][2] + bb0), gelu_f(acc[mi][ni][3] + bb1));
        }
        *(uint4*)(g_h + r0*KDIM + cbase)     = v0;
        *(uint4*)(g_h + (r0+8)*KDIM + cbase) = v1;
    }
}

// ---------------- fp16 edge stage (slice): cp.async P + double-buffered h ----------------
#define PST 264
#define HST 264
#define EDGE_SMEM ((LDIM*PST + 2*16*HST)*2 + LDIM*4 + MAXDEG*8)

__global__ __launch_bounds__(256) void k_edge(const int* __restrict__ ei,
                                              float* __restrict__ agg, int n0base)
{
    extern __shared__ __half smh[];
    __half* Ps   = smh;                          // [64][264]
    __half* hs0  = smh + LDIM*PST;               // 2 x [16][264]
    float*  xb3s = (float*)(hs0 + 2*16*HST);     // [64]
    int*    earr = (int*)(xb3s + LDIM);          // [128]
    int*    dsts = earr + MAXDEG;                // [128]

    int nl = blockIdx.x;                          // local slice row
    int n  = n0base + nl;                         // global node
    int deg = g_deg[n];
    if (deg == 0) return;

    int t = threadIdx.x;
    int lane = t & 31, warp = t >> 5;
    int g = lane >> 2, tg = lane & 3;
    int n0 = warp * 8;

    const __half* Png = g_P + (size_t)nl * KL;
    #pragma unroll
    for (int i = t; i < KL/8; i += 256){
        int o = i >> 5, kp = (i & 31) << 3;
        cp16(&Ps[o*PST + kp], Png + (o << 8) + kp);
    }
    cp_commit();
    if (t < LDIM) xb3s[t] = g_xb3[n*LDIM + t];

    int ra  = (lane & 7) + ((lane >> 3) & 1) * 8;
    int ca  = ((lane >> 4) & 1) * 8;
    int rb2 = (lane & 7);
    int cb2 = ((lane >> 3) & 1) * 8;

    for (int i = t; i < deg; i += 256){
        int e = g_csr[n*MAXDEG + i];
        earr[i] = e;
        dsts[i] = ei[N_EDGES + e];
    }
    __syncthreads();
    int nch = (deg + 15) >> 4;

    {
        __half* hb = hs0;
        #pragma unroll
        for (int q = 0; q < 2; q++){
            int i = t + q*256;
            int slot = i >> 5, seg = i & 31;
            int eidx = slot; if (eidx >= deg) eidx = deg - 1;
            cp16(&hb[slot*HST + (seg<<3)], g_h + (size_t)earr[eidx]*KDIM + (seg<<3));
        }
        cp_commit();
    }
    for (int c = 0; c < nch; c++){
        if (c + 1 < nch){
            __half* hb = hs0 + ((c+1)&1)*16*HST;
            int base = (c+1)*16;
            #pragma unroll
            for (int q = 0; q < 2; q++){
                int i = t + q*256;
                int slot = i >> 5, seg = i & 31;
                int eidx = base + slot; if (eidx >= deg) eidx = deg - 1;
                cp16(&hb[slot*HST + (seg<<3)], g_h + (size_t)earr[eidx]*KDIM + (seg<<3));
            }
            cp_commit();
            cp_wait<1>();
        } else {
            cp_wait<0>();
        }
        __syncthreads();

        const __half* hs = hs0 + (c&1)*16*HST;
        int csz = min(16, deg - c*16);
        float acc[4] = {0,0,0,0};
        #pragma unroll
        for (int ks = 0; ks < KDIM; ks += 16){
            uint32_t a[4], b[2];
            ldsm_x4(a, smaddr(&hs[ra*HST + ks + ca]));
            ldsm_x2(b, smaddr(&Ps[(n0 + rb2)*PST + ks + cb2]));
            mma16(acc, a, b);
        }
        int s0 = c*16;
        int cc = n0 + (tg<<1);
        float x0 = xb3s[cc], x1 = xb3s[cc+1];
        if (g < csz){
            int d = dsts[s0 + g];
            atomicAdd(&agg[(size_t)d*LDIM + cc    ], acc[0] + x0);
            atomicAdd(&agg[(size_t)d*LDIM + cc + 1], acc[1] + x1);
        }
        if (g + 8 < csz){
            int d = dsts[s0 + g + 8];
            atomicAdd(&agg[(size_t)d*LDIM + cc    ], acc[2] + x0);
            atomicAdd(&agg[(size_t)d*LDIM + cc + 1], acc[3] + x1);
        }
        __syncthreads();
    }
}

// ---------------- conv boundary: x1 = gelu(x@Wr + agg + bias), xh, xb3 = x1@B3 ----------------
__global__ __launch_bounds__(256) void k_boundary(
    const float* __restrict__ x, const float* __restrict__ Wr,
    const float* __restrict__ agg, const float* __restrict__ bias,
    const float* __restrict__ b3,
    float* __restrict__ x1, __half* __restrict__ xh, float* __restrict__ xb3)
{
    __shared__ float xs[4*LDIM];
    __shared__ float xs2[4*LDIM];
    int t = threadIdx.x;
    int o = t & 63, loc = t >> 6;
    int n0 = blockIdx.x * 4;
    xs[t] = x[(size_t)n0*LDIM + t];
    __syncthreads();
    int n = n0 + loc;
    float v = 0.f;
    #pragma unroll 8
    for (int i = 0; i < LDIM; i++) v += xs[loc*LDIM + i] * __ldg(&Wr[i*LDIM + o]);
    v += agg[(size_t)n*LDIM + o] + bias[o];
    v = gelu_f(v);
    x1[(size_t)n*LDIM + o] = v;
    xh[(size_t)n*LDIM + o] = __float2half_rn(v);
    xs2[t] = v;
    __syncthreads();
    float w = 0.f;
    #pragma unroll 8
    for (int i = 0; i < LDIM; i++) w += xs2[loc*LDIM + i] * __ldg(&b3[i*LDIM + o]);
    xb3[(size_t)n*LDIM + o] = w;
}

// ---------------- final node matmul: out = x @ Wr + agg + bias ----------------
__global__ __launch_bounds__(256) void k_final(
    const float* __restrict__ x, const float* __restrict__ Wr,
    const float* __restrict__ agg, const float* __restrict__ bias,
    float* __restrict__ out)
{
    __shared__ float xs[4*LDIM];
    int t = threadIdx.x;
    int o = t & 63, loc = t >> 6;
    int n0 = blockIdx.x * 4;
    xs[t] = x[(size_t)n0*LDIM + t];
    __syncthreads();
    int n = n0 + loc;
    float v = 0.f;
    #pragma unroll 8
    for (int i = 0; i < LDIM; i++) v += xs[loc*LDIM + i] * __ldg(&Wr[i*LDIM + o]);
    v += agg[(size_t)n*LDIM + o] + bias[o];
    out[(size_t)n*LDIM + o] = v;
}

// ---------------- launch ----------------
extern "C" void kernel_launch(void* const* d_in, const int* in_sizes, int n_in,
                              void* d_out, int out_size)
{
    const float* nodes = (const float*)d_in[0];
    const int*   ei    = (const int*)  d_in[1];
    const float* ea    = (const float*)d_in[2];
    const float* W1    = (const float*)d_in[3];
    const float* b1    = (const float*)d_in[4];
    const float* W2    = (const float*)d_in[5];
    const float* b2    = (const float*)d_in[6];
    const float* W3    = (const float*)d_in[7];
    const float* b3    = (const float*)d_in[8];
    const float* Wr    = (const float*)d_in[9];
    const float* bias  = (const float*)d_in[10];
    float* out = (float*)d_out;

    __half *pP, *pXh;
    float *pX1, *pXb3, *pAgg, *pAgg2;
    cudaGetSymbolAddress((void**)&pP,    g_P);
    cudaGetSymbolAddress((void**)&pXh,   g_xh);
    cudaGetSymbolAddress((void**)&pX1,   g_x1);
    cudaGetSymbolAddress((void**)&pXb3,  g_xb3);
    cudaGetSymbolAddress((void**)&pAgg,  g_agg);
    cudaGetSymbolAddress((void**)&pAgg2, g_agg2);

    static int smem_set = 0;
    if (!smem_set){
        cudaFuncSetAttribute(k_edge, cudaFuncAttributeMaxDynamicSharedMemorySize, EDGE_SMEM);
        smem_set = 1;
    }

    dim3 pgrid(KL/BNt, SLICE_N/BMt);

    k_prep    <<<(KL*LDIM)/256, 256>>>(W3, W2, nodes, b3);                     // 0
    k_hgemm   <<<dim3(KDIM/BNt, N_EDGES/BMt), 256>>>(ea, W1, b1, b2, ei);      // 1 (+ CSR bucket)

    // ---- conv 1: slice-interleaved (P slice stays L2-resident) ----
    k_gemmP   <<<pgrid, 256>>>(pXh, pP, 0);                                    // 2
    k_edge    <<<SLICE_N, 256, EDGE_SMEM>>>(ei, pAgg, 0);                      // 3  <-- profiled
    k_gemmP   <<<pgrid, 256>>>(pXh, pP, SLICE_N);                              // 4
    k_edge    <<<SLICE_N, 256, EDGE_SMEM>>>(ei, pAgg, SLICE_N);                // 5
    k_boundary<<<N_NODES/4, 256>>>(nodes, Wr, pAgg, bias, b3, pX1, pXh, pXb3); // 6

    // ---- conv 2 ----
    k_gemmP   <<<pgrid, 256>>>(pXh, pP, 0);                                    // 7
    k_edge    <<<SLICE_N, 256, EDGE_SMEM>>>(ei, pAgg2, 0);                     // 8
    k_gemmP   <<<pgrid, 256>>>(pXh, pP, SLICE_N);                              // 9
    k_edge    <<<SLICE_N, 256, EDGE_SMEM>>>(ei, pAgg2, SLICE_N);               // 10
    k_final   <<<N_NODES/4, 256>>>(pX1, Wr, pAgg2, bias, out);                 // 11
}

// round 14
// speedup vs baseline: 1.0054x; 1.0054x over previous
#include <cuda_runtime.h>
#include <cuda_fp16.h>
#include <cstdint>

#define N_NODES 4096
#define N_EDGES 65536
#define LDIM 64
#define KDIM 256
#define EDIM 6
#define KL (KDIM*LDIM)   /* 16384 */
#define MAXDEG 128       /* bucket capacity; Poisson(16) => P(deg>128) ~ 0 */

// Layout note: g_P and g_h use a PERMUTED k-order (warp-tile-relative
// tg*8+ni*2+half), identical in both producers; k_edge contracts
// position-by-position so the dot over k is unchanged. o is NOT permuted.

// ---------------- scratch (device globals; no runtime allocation) ----------------
__device__ __half g_W3pT[(size_t)KL*LDIM];        // [col=o*256+k][i]  fp16, 2 MB
__device__ __half g_W2T[KDIM*KDIM];               // [n][k] fp16
__device__ __half g_xh[N_NODES*LDIM];             // fp16 copy of current x
__device__ __half g_h [(size_t)N_EDGES*KDIM];     // 32 MB fp16 (permuted k)
__device__ __half g_P [(size_t)N_NODES*KL];       // 128 MB fp16, [n][o][permuted k]
__device__ float  g_x1 [N_NODES*LDIM];
__device__ float  g_xb3[N_NODES*LDIM];
__device__ float  g_agg [N_NODES*LDIM];
__device__ float  g_agg2[N_NODES*LDIM];
__device__ int    g_deg[N_NODES];
__device__ int    g_csr[N_NODES*MAXDEG];          // bucketed edge ids (2 MB)

// ---------------- helpers ----------------
__device__ __forceinline__ float gelu_f(float x){
    return 0.5f * x * (1.0f + erff(x * 0.70710678118654752440f));
}
__device__ __forceinline__ void mma16(float* c, const uint32_t* a, const uint32_t* b){
    asm volatile(
        "mma.sync.aligned.m16n8k16.row.col.f32.f16.f16.f32 "
        "{%0,%1,%2,%3}, {%4,%5,%6,%7}, {%8,%9}, {%0,%1,%2,%3};\n"
        : "+f"(c[0]), "+f"(c[1]), "+f"(c[2]), "+f"(c[3])
        : "r"(a[0]), "r"(a[1]), "r"(a[2]), "r"(a[3]), "r"(b[0]), "r"(b[1]));
}
__device__ __forceinline__ uint32_t smaddr(const void* p){
    return (uint32_t)__cvta_generic_to_shared(p);
}
__device__ __forceinline__ void ldsm_x4(uint32_t* r, uint32_t a){
    asm volatile("ldmatrix.sync.aligned.m8n8.x4.shared.b16 {%0,%1,%2,%3}, [%4];"
        : "=r"(r[0]), "=r"(r[1]), "=r"(r[2]), "=r"(r[3]) : "r"(a));
}
__device__ __forceinline__ void ldsm_x2(uint32_t* r, uint32_t a){
    asm volatile("ldmatrix.sync.aligned.m8n8.x2.shared.b16 {%0,%1}, [%2];"
        : "=r"(r[0]), "=r"(r[1]) : "r"(a));
}
__device__ __forceinline__ void cp16(void* smem_dst, const void* gsrc){
    asm volatile("cp.async.cg.shared.global [%0], [%1], 16;\n"
                 :: "r"(smaddr(smem_dst)), "l"(gsrc));
}
__device__ __forceinline__ void cp_commit(){
    asm volatile("cp.async.commit_group;\n");
}
template<int N> __device__ __forceinline__ void cp_wait(){
    asm volatile("cp.async.wait_group %0;\n" :: "n"(N));
}

// ---------------- fused prep: W3/W2 fp16 transposes, x->fp16, xb3, zero agg/deg ----------------
__global__ void k_prep(const float* __restrict__ W3, const float* __restrict__ W2,
                       const float* __restrict__ nodes, const float* __restrict__ b3){
    int idx = blockIdx.x*256 + threadIdx.x;        // 0 .. 1048575
    {   // W3pT[(o*256+k)*64 + i] = W3[k, i*64+o]
        int col = idx >> 6, i = idx & 63;
        int o = col >> 8, k = col & 255;
        g_W3pT[idx] = __float2half_rn(W3[k*(LDIM*LDIM) + i*LDIM + o]);
    }
    if (idx < KDIM*KDIM){
        int n = idx >> 8, k = idx & 255;
        g_W2T[idx] = __float2half_rn(W2[k*KDIM + n]);
    }
    if (idx < N_NODES*LDIM){
        g_agg[idx]  = 0.f;
        g_agg2[idx] = 0.f;
        g_xh[idx]   = __float2half_rn(nodes[idx]);
        int n = idx >> 6, o = idx & 63;
        const float* xr = nodes + n*LDIM;
        float v = 0.f;
        #pragma unroll 8
        for (int i = 0; i < LDIM; i++) v += xr[i] * __ldg(&b3[i*LDIM + o]);
        g_xb3[idx] = v;
    }
    if (idx < N_NODES) g_deg[idx] = 0;
}

// ---------------- fp16 GEMM for P: cp.async staging, permuted coalesced epilogue ----------------
#define BMt 128
#define BNt 128
#define PAST 72

__global__ __launch_bounds__(256, 3) void k_gemmP(
    const __half* __restrict__ A, __half* __restrict__ C)
{
    __shared__ __half As[BMt*PAST];
    __shared__ __half Bs[BNt*PAST];
    const int N = KL, K = LDIM;
    int tid = threadIdx.x;
    int lane = tid & 31, warp = tid >> 5;
    int g = lane >> 2, tg = lane & 3;
    int wm = (warp >> 2) * 64;
    int wn = (warp & 3) * 32;
    size_t bm0 = (size_t)blockIdx.y * BMt;
    size_t bn0 = (size_t)blockIdx.x * BNt;

    #pragma unroll
    for (int i = tid; i < BMt*8; i += 256){
        int r = i >> 3, s = (i & 7) << 3;
        cp16(&As[r*PAST + s], A + (bm0 + r)*K + s);
    }
    #pragma unroll
    for (int i = tid; i < BNt*8; i += 256){
        int r = i >> 3, s = (i & 7) << 3;
        cp16(&Bs[r*PAST + s], g_W3pT + (size_t)(bn0 + r)*K + s);
    }
    cp_commit();

    float acc[4][4][4];
    #pragma unroll
    for (int a=0;a<4;a++)
        #pragma unroll
        for (int b=0;b<4;b++)
            #pragma unroll
            for (int c=0;c<4;c++) acc[a][b][c] = 0.f;

    int ra = (lane & 7) + ((lane >> 3) & 1) * 8;
    int ca = ((lane >> 4) & 1) * 8;
    int rb = (lane & 7) + ((lane >> 4) & 1) * 8;
    int cb = ((lane >> 3) & 1) * 8;

    cp_wait<0>();
    __syncthreads();

    #pragma unroll
    for (int kk = 0; kk < K; kk += 16){
        uint32_t af[4][4], bf[4][2];
        #pragma unroll
        for (int mi=0; mi<4; mi++)
            ldsm_x4(af[mi], smaddr(&As[(wm + mi*16 + ra)*PAST + kk + ca]));
        #pragma unroll
        for (int p=0; p<2; p++){
            uint32_t r4[4];
            ldsm_x4(r4, smaddr(&Bs[(wn + p*16 + rb)*PAST + kk + cb]));
            bf[2*p  ][0] = r4[0]; bf[2*p  ][1] = r4[1];
            bf[2*p+1][0] = r4[2]; bf[2*p+1][1] = r4[3];
        }
        #pragma unroll
        for (int mi=0; mi<4; mi++)
            #pragma unroll
            for (int ni=0; ni<4; ni++)
                mma16(acc[mi][ni], af[mi], bf[ni]);
    }

    size_t cbase = bn0 + wn + tg*8;
    #pragma unroll
    for (int mi=0; mi<4; mi++){
        size_t r0 = bm0 + wm + mi*16 + g;
        uint4 v0, v1;
        __half2* p0 = (__half2*)&v0;
        __half2* p1 = (__half2*)&v1;
        #pragma unroll
        for (int ni=0; ni<4; ni++){
            p0[ni] = __floats2half2_rn(acc[mi][ni][0], acc[mi][ni][1]);
            p1[ni] = __floats2half2_rn(acc[mi][ni][2], acc[mi][ni][3]);
        }
        *(uint4*)(C + r0*N + cbase)     = v0;
        *(uint4*)(C + (r0+8)*N + cbase) = v1;
    }
}

// ---------------- fused h GEMM (fp16) + edge bucketing prologue ----------------
#define HAST 40
#define HBKT 32

__global__ __launch_bounds__(256) void k_hgemm(
    const float* __restrict__ ea, const float* __restrict__ W1, const float* __restrict__ b1,
    const float* __restrict__ b2, const int* __restrict__ ei)
{
    __shared__ __half As[BMt*HAST];
    __shared__ __half Bs[BMt*HAST];
    __shared__ float eas[BMt*EDIM];
    __shared__ float W1s[EDIM*KDIM];
    __shared__ float b1s[KDIM];
    int tid = threadIdx.x;

    // ---- bucket CSR build: 1024 blocks x 256 threads >= 65536 edges ----
    {
        int gtid = (blockIdx.y * gridDim.x + blockIdx.x) * 256 + tid;
        if (gtid < N_EDGES){
            int s = ei[gtid];
            int slot = atomicAdd(&g_deg[s], 1);
            g_csr[s*MAXDEG + slot] = gtid;
        }
    }

    int lane = tid & 31, warp = tid >> 5;
    int g = lane >> 2, tg = lane & 3;
    int wm = (warp >> 2) * 64;
    int wn = (warp & 3) * 32;
    size_t bm0 = (size_t)blockIdx.y * BMt;
    size_t bn0 = (size_t)blockIdx.x * BNt;

    for (int i = tid; i < BMt*EDIM; i += 256) eas[i] = ea[bm0*EDIM + i];
    for (int i = tid; i < EDIM*KDIM; i += 256) W1s[i] = W1[i];
    if (tid < KDIM) b1s[tid] = b1[tid];

    float acc[4][4][4];
    #pragma unroll
    for (int a=0;a<4;a++)
        #pragma unroll
        for (int b=0;b<4;b++)
            #pragma unroll
            for (int c=0;c<4;c++) acc[a][b][c] = 0.f;

    int ra = (lane & 7) + ((lane >> 3) & 1) * 8;
    int ca = ((lane >> 4) & 1) * 8;
    int rb = (lane & 7) + ((lane >> 4) & 1) * 8;
    int cb = ((lane >> 3) & 1) * 8;

    __syncthreads();

    for (int k0 = 0; k0 < KDIM; k0 += HBKT){
        #pragma unroll
        for (int i = tid; i < BMt*4; i += 256){
            int r = i >> 2, s = (i & 3) << 3;
            cp16(&Bs[r*HAST + s], g_W2T + (size_t)(bn0 + r)*KDIM + k0 + s);
        }
        cp_commit();
        {
            int c = tid & 31;
            int rg = tid >> 5;
            float w0 = W1s[0*KDIM + k0 + c], w1 = W1s[1*KDIM + k0 + c];
            float w2 = W1s[2*KDIM + k0 + c], w3 = W1s[3*KDIM + k0 + c];
            float w4 = W1s[4*KDIM + k0 + c], w5 = W1s[5*KDIM + k0 + c];
            float bb = b1s[k0 + c];
            #pragma unroll
            for (int i = 0; i < 16; i++){
                int r = rg*16 + i;
                const float* er = &eas[r*EDIM];
                float v = bb + er[0]*w0 + er[1]*w1 + er[2]*w2 + er[3]*w3 + er[4]*w4 + er[5]*w5;
                As[r*HAST + c] = __float2half_rn(gelu_f(v));
            }
        }
        cp_wait<0>();
        __syncthreads();
        #pragma unroll
        for (int kk = 0; kk < HBKT; kk += 16){
            uint32_t af[4][4], bf[4][2];
            #pragma unroll
            for (int mi=0; mi<4; mi++)
                ldsm_x4(af[mi], smaddr(&As[(wm + mi*16 + ra)*HAST + kk + ca]));
            #pragma unroll
            for (int p=0; p<2; p++){
                uint32_t r4[4];
                ldsm_x4(r4, smaddr(&Bs[(wn + p*16 + rb)*HAST + kk + cb]));
                bf[2*p  ][0] = r4[0]; bf[2*p  ][1] = r4[1];
                bf[2*p+1][0] = r4[2]; bf[2*p+1][1] = r4[3];
            }
            #pragma unroll
            for (int mi=0; mi<4; mi++)
                #pragma unroll
                for (int ni=0; ni<4; ni++)
                    mma16(acc[mi][ni], af[mi], bf[ni]);
        }
        __syncthreads();
    }

    size_t cbase = bn0 + wn + tg*8;
    #pragma unroll
    for (int mi=0; mi<4; mi++){
        size_t r0 = bm0 + wm + mi*16 + g;
        uint4 v0, v1;
        __half2* p0 = (__half2*)&v0;
        __half2* p1 = (__half2*)&v1;
        #pragma unroll
        for (int ni=0; ni<4; ni++){
            int cg = (int)bn0 + wn + ni*8 + (tg<<1);
            float bb0 = b2[cg], bb1 = b2[cg+1];
            p0[ni] = __floats2half2_rn(gelu_f(acc[mi][ni][0] + bb0), gelu_f(acc[mi][ni][1] + bb1));
            p1[ni] = __floats2half2_rn(gelu_f(acc[mi][ni][2] + bb0), gelu_f(acc[mi][ni][3] + bb1));
        }
        *(uint4*)(g_h + r0*KDIM + cbase)     = v0;
        *(uint4*)(g_h + (r0+8)*KDIM + cbase) = v1;
    }
}

// ---------------- fp16 edge stage: single h buffer (smaller smem -> 5 CTAs/SM) ----------------
#define PST 264
#define HST 264
#define EDGE_SMEM ((LDIM*PST + 16*HST)*2 + LDIM*4 + MAXDEG*8)

__global__ __launch_bounds__(256, 5) void k_edge(const int* __restrict__ ei,
                                                 float* __restrict__ agg)
{
    extern __shared__ __half smh[];
    __half* Ps   = smh;                          // [64][264]
    __half* hs   = smh + LDIM*PST;               // [16][264]
    float*  xb3s = (float*)(hs + 16*HST);        // [64]
    int*    earr = (int*)(xb3s + LDIM);          // [128]
    int*    dsts = earr + MAXDEG;                // [128]

    int n = blockIdx.x;
    int deg = g_deg[n];
    if (deg == 0) return;

    int t = threadIdx.x;
    int lane = t & 31, warp = t >> 5;
    int g = lane >> 2, tg = lane & 3;
    int n0 = warp * 8;

    // stage P_n via cp.async (own group)
    const __half* Png = g_P + (size_t)n * KL;
    #pragma unroll
    for (int i = t; i < KL/8; i += 256){
        int o = i >> 5, kp = (i & 31) << 3;
        cp16(&Ps[o*PST + kp], Png + (o << 8) + kp);
    }
    cp_commit();
    if (t < LDIM) xb3s[t] = g_xb3[n*LDIM + t];

    int ra  = (lane & 7) + ((lane >> 3) & 1) * 8;
    int ca  = ((lane >> 4) & 1) * 8;
    int rb2 = (lane & 7);
    int cb2 = ((lane >> 3) & 1) * 8;

    for (int i = t; i < deg; i += 256){
        int e = g_csr[n*MAXDEG + i];
        earr[i] = e;
        dsts[i] = ei[N_EDGES + e];
    }
    __syncthreads();
    int nch = (deg + 15) >> 4;

    for (int c = 0; c < nch; c++){
        // stage h chunk c (single buffer)
        int base = c*16;
        #pragma unroll
        for (int q = 0; q < 2; q++){
            int i = t + q*256;
            int slot = i >> 5, seg = i & 31;
            int eidx = base + slot; if (eidx >= deg) eidx = deg - 1;
            cp16(&hs[slot*HST + (seg<<3)], g_h + (size_t)earr[eidx]*KDIM + (seg<<3));
        }
        cp_commit();
        cp_wait<0>();          // drains P (first iter) + h chunk
        __syncthreads();

        int csz = min(16, deg - base);
        float acc[4] = {0,0,0,0};
        #pragma unroll
        for (int ks = 0; ks < KDIM; ks += 16){
            uint32_t a[4], b[2];
            ldsm_x4(a, smaddr(&hs[ra*HST + ks + ca]));
            ldsm_x2(b, smaddr(&Ps[(n0 + rb2)*PST + ks + cb2]));
            mma16(acc, a, b);
        }
        int cc = n0 + (tg<<1);
        float x0 = xb3s[cc], x1 = xb3s[cc+1];
        if (g < csz){
            int d = dsts[base + g];
            atomicAdd(&agg[(size_t)d*LDIM + cc    ], acc[0] + x0);
            atomicAdd(&agg[(size_t)d*LDIM + cc + 1], acc[1] + x1);
        }
        if (g + 8 < csz){
            int d = dsts[base + g + 8];
            atomicAdd(&agg[(size_t)d*LDIM + cc    ], acc[2] + x0);
            atomicAdd(&agg[(size_t)d*LDIM + cc + 1], acc[3] + x1);
        }
        __syncthreads();       // hs consumed before next chunk overwrite
    }
}

// ---------------- conv boundary: x1 = gelu(x@Wr + agg + bias), xh, xb3 = x1@B3 ----------------
__global__ __launch_bounds__(256) void k_boundary(
    const float* __restrict__ x, const float* __restrict__ Wr,
    const float* __restrict__ agg, const float* __restrict__ bias,
    const float* __restrict__ b3,
    float* __restrict__ x1, __half* __restrict__ xh, float* __restrict__ xb3)
{
    __shared__ float xs[4*LDIM];
    __shared__ float xs2[4*LDIM];
    int t = threadIdx.x;
    int o = t & 63, loc = t >> 6;
    int n0 = blockIdx.x * 4;
    xs[t] = x[(size_t)n0*LDIM + t];
    __syncthreads();
    int n = n0 + loc;
    float v = 0.f;
    #pragma unroll 8
    for (int i = 0; i < LDIM; i++) v += xs[loc*LDIM + i] * __ldg(&Wr[i*LDIM + o]);
    v += agg[(size_t)n*LDIM + o] + bias[o];
    v = gelu_f(v);
    x1[(size_t)n*LDIM + o] = v;
    xh[(size_t)n*LDIM + o] = __float2half_rn(v);
    xs2[t] = v;
    __syncthreads();
    float w = 0.f;
    #pragma unroll 8
    for (int i = 0; i < LDIM; i++) w += xs2[loc*LDIM + i] * __ldg(&b3[i*LDIM + o]);
    xb3[(size_t)n*LDIM + o] = w;
}

// ---------------- final node matmul: out = x @ Wr + agg + bias ----------------
__global__ __launch_bounds__(256) void k_final(
    const float* __restrict__ x, const float* __restrict__ Wr,
    const float* __restrict__ agg, const float* __restrict__ bias,
    float* __restrict__ out)
{
    __shared__ float xs[4*LDIM];
    int t = threadIdx.x;
    int o = t & 63, loc = t >> 6;
    int n0 = blockIdx.x * 4;
    xs[t] = x[(size_t)n0*LDIM + t];
    __syncthreads();
    int n = n0 + loc;
    float v = 0.f;
    #pragma unroll 8
    for (int i = 0; i < LDIM; i++) v += xs[loc*LDIM + i] * __ldg(&Wr[i*LDIM + o]);
    v += agg[(size_t)n*LDIM + o] + bias[o];
    out[(size_t)n*LDIM + o] = v;
}

// ---------------- launch ----------------
extern "C" void kernel_launch(void* const* d_in, const int* in_sizes, int n_in,
                              void* d_out, int out_size)
{
    const float* nodes = (const float*)d_in[0];
    const int*   ei    = (const int*)  d_in[1];
    const float* ea    = (const float*)d_in[2];
    const float* W1    = (const float*)d_in[3];
    const float* b1    = (const float*)d_in[4];
    const float* W2    = (const float*)d_in[5];
    const float* b2    = (const float*)d_in[6];
    const float* W3    = (const float*)d_in[7];
    const float* b3    = (const float*)d_in[8];
    const float* Wr    = (const float*)d_in[9];
    const float* bias  = (const float*)d_in[10];
    float* out = (float*)d_out;

    __half *pP, *pXh;
    float *pX1, *pXb3, *pAgg, *pAgg2;
    cudaGetSymbolAddress((void**)&pP,    g_P);
    cudaGetSymbolAddress((void**)&pXh,   g_xh);
    cudaGetSymbolAddress((void**)&pX1,   g_x1);
    cudaGetSymbolAddress((void**)&pXb3,  g_xb3);
    cudaGetSymbolAddress((void**)&pAgg,  g_agg);
    cudaGetSymbolAddress((void**)&pAgg2, g_agg2);

    static int smem_set = 0;
    if (!smem_set){
        cudaFuncSetAttribute(k_edge, cudaFuncAttributeMaxDynamicSharedMemorySize, EDGE_SMEM);
        smem_set = 1;
    }

    k_prep    <<<(KL*LDIM)/256, 256>>>(W3, W2, nodes, b3);                     // 0
    k_hgemm   <<<dim3(KDIM/BNt, N_EDGES/BMt), 256>>>(ea, W1, b1, b2, ei);      // 1 (+ CSR bucket)
    k_gemmP   <<<dim3(KL/BNt, N_NODES/BMt), 256>>>(pXh, pP);                   // 2 (conv1 P)
    k_edge    <<<N_NODES, 256, EDGE_SMEM>>>(ei, pAgg);                         // 3  <-- profiled
    k_boundary<<<N_NODES/4, 256>>>(nodes, Wr, pAgg, bias, b3, pX1, pXh, pXb3); // 4
    k_gemmP   <<<dim3(KL/BNt, N_NODES/BMt), 256>>>(pXh, pP);                   // 5 (conv2 P)
    k_edge    <<<N_NODES, 256, EDGE_SMEM>>>(ei, pAgg2);                        // 6
    k_final   <<<N_NODES/4, 256>>>(pX1, Wr, pAgg2, bias, out);                 // 7
}

// round 15
// speedup vs baseline: 1.0127x; 1.0072x over previous
#include <cuda_runtime.h>
#include <cuda_fp16.h>
#include <cstdint>

#define N_NODES 4096
#define N_EDGES 65536
#define LDIM 64
#define KDIM 256
#define EDIM 6
#define KL (KDIM*LDIM)   /* 16384 */
#define MAXDEG 128       /* bucket capacity; Poisson(16) => P(deg>128) ~ 0 */

// Layout notes:
//  - g_h uses the warp-tile-permuted slot order (hgemm epilogue), as before.
//  - g_P is stored in mma-B-FRAGMENT order: half-offset within a node row =
//      og*2048 + p*256 + lane*8 + pos,  og=o>>3, p=ks-pair, lane=no*4+j,
//      pos = (kb&1)*4 + (kp>>3)*2 + (kp&1)   (kp = 2j,2j+1,2j+8,2j+9)
//    k_prep bakes BOTH this mapping and the gemmP-epilogue tile permutation
//    (involution sigma) into W3pT's column order, so k_gemmP is unchanged.
//  - k_edge loads B fragments for its warp directly via 8 coalesced LDG.128
//    per lane into registers; no P smem stage at all.

// ---------------- scratch (device globals; no runtime allocation) ----------------
__device__ __half g_W3pT[(size_t)KL*LDIM];        // fragment/sigma-permuted cols, fp16, 2 MB
__device__ __half g_W2T[KDIM*KDIM];               // [n][k] fp16
__device__ __half g_xh[N_NODES*LDIM];             // fp16 copy of current x
__device__ __half g_h [(size_t)N_EDGES*KDIM];     // 32 MB fp16 (permuted slots)
__device__ __half g_P [(size_t)N_NODES*KL];       // 128 MB fp16, fragment order
__device__ float  g_x1 [N_NODES*LDIM];
__device__ float  g_xb3[N_NODES*LDIM];
__device__ float  g_agg [N_NODES*LDIM];
__device__ float  g_agg2[N_NODES*LDIM];
__device__ int    g_deg[N_NODES];
__device__ int    g_csr[N_NODES*MAXDEG];          // bucketed edge ids (2 MB)

// ---------------- helpers ----------------
__device__ __forceinline__ float gelu_f(float x){
    return 0.5f * x * (1.0f + erff(x * 0.70710678118654752440f));
}
__device__ __forceinline__ void mma16(float* c, const uint32_t* a, const uint32_t* b){
    asm volatile(
        "mma.sync.aligned.m16n8k16.row.col.f32.f16.f16.f32 "
        "{%0,%1,%2,%3}, {%4,%5,%6,%7}, {%8,%9}, {%0,%1,%2,%3};\n"
        : "+f"(c[0]), "+f"(c[1]), "+f"(c[2]), "+f"(c[3])
        : "r"(a[0]), "r"(a[1]), "r"(a[2]), "r"(a[3]), "r"(b[0]), "r"(b[1]));
}
__device__ __forceinline__ uint32_t smaddr(const void* p){
    return (uint32_t)__cvta_generic_to_shared(p);
}
__device__ __forceinline__ void ldsm_x4(uint32_t* r, uint32_t a){
    asm volatile("ldmatrix.sync.aligned.m8n8.x4.shared.b16 {%0,%1,%2,%3}, [%4];"
        : "=r"(r[0]), "=r"(r[1]), "=r"(r[2]), "=r"(r[3]) : "r"(a));
}
__device__ __forceinline__ void cp16(void* smem_dst, const void* gsrc){
    asm volatile("cp.async.cg.shared.global [%0], [%1], 16;\n"
                 :: "r"(smaddr(smem_dst)), "l"(gsrc));
}
__device__ __forceinline__ void cp_commit(){
    asm volatile("cp.async.commit_group;\n");
}
template<int N> __device__ __forceinline__ void cp_wait(){
    asm volatile("cp.async.wait_group %0;\n" :: "n"(N));
}
// warp-tile store permutation (involution): v = ni*8+2tg+half <-> tg*8+ni*2+half
__device__ __forceinline__ int sigma32(int v){
    return (((v & 7) >> 1) << 3) + ((v >> 3) << 1) + (v & 1);
}

// ---------------- fused prep: W3/W2 fp16 transposes, x->fp16, xb3, zero agg/deg ----------------
__global__ void k_prep(const float* __restrict__ W3, const float* __restrict__ W2,
                       const float* __restrict__ nodes, const float* __restrict__ b3){
    int idx = blockIdx.x*256 + threadIdx.x;        // 0 .. 1048575
    {
        int col = idx >> 6, i = idx & 63;          // gemm column c', row i
        // 1) gemmP epilogue permutation: logical col c' is STORED at address a
        int a = (col & ~31) | sigma32(col & 31);
        // 2) decompose address a under the fragment layout -> (o, slot)
        int og   = a >> 11;
        int rem  = a & 2047;
        int p    = rem >> 8;
        int rem2 = rem & 255;
        int lane = rem2 >> 3;
        int pos  = rem2 & 7;
        int no = lane >> 2, j = lane & 3;
        int w2 = pos >> 2,  pb = pos & 3;
        int kp   = ((pb >> 1) << 3) + (j << 1) + (pb & 1);
        int slot = ((p << 1) + w2) * 16 + kp;
        // 3) slot -> logical k (hgemm epilogue permutation, same involution)
        int k_log = (slot & ~31) | sigma32(slot & 31);
        int o = (og << 3) + no;
        g_W3pT[idx] = __float2half_rn(W3[k_log*(LDIM*LDIM) + i*LDIM + o]);
    }
    if (idx < KDIM*KDIM){
        int n = idx >> 8, k = idx & 255;
        g_W2T[idx] = __float2half_rn(W2[k*KDIM + n]);
    }
    if (idx < N_NODES*LDIM){
        g_agg[idx]  = 0.f;
        g_agg2[idx] = 0.f;
        g_xh[idx]   = __float2half_rn(nodes[idx]);
        int n = idx >> 6, o = idx & 63;
        const float* xr = nodes + n*LDIM;
        float v = 0.f;
        #pragma unroll 8
        for (int i = 0; i < LDIM; i++) v += xr[i] * __ldg(&b3[i*LDIM + o]);
        g_xb3[idx] = v;
    }
    if (idx < N_NODES) g_deg[idx] = 0;
}

// ---------------- fp16 GEMM for P: cp.async staging, permuted coalesced epilogue ----------------
#define BMt 128
#define BNt 128
#define PAST 72

__global__ __launch_bounds__(256, 3) void k_gemmP(
    const __half* __restrict__ A, __half* __restrict__ C)
{
    __shared__ __half As[BMt*PAST];
    __shared__ __half Bs[BNt*PAST];
    const int N = KL, K = LDIM;
    int tid = threadIdx.x;
    int lane = tid & 31, warp = tid >> 5;
    int g = lane >> 2, tg = lane & 3;
    int wm = (warp >> 2) * 64;
    int wn = (warp & 3) * 32;
    size_t bm0 = (size_t)blockIdx.y * BMt;
    size_t bn0 = (size_t)blockIdx.x * BNt;

    #pragma unroll
    for (int i = tid; i < BMt*8; i += 256){
        int r = i >> 3, s = (i & 7) << 3;
        cp16(&As[r*PAST + s], A + (bm0 + r)*K + s);
    }
    #pragma unroll
    for (int i = tid; i < BNt*8; i += 256){
        int r = i >> 3, s = (i & 7) << 3;
        cp16(&Bs[r*PAST + s], g_W3pT + (size_t)(bn0 + r)*K + s);
    }
    cp_commit();

    float acc[4][4][4];
    #pragma unroll
    for (int a=0;a<4;a++)
        #pragma unroll
        for (int b=0;b<4;b++)
            #pragma unroll
            for (int c=0;c<4;c++) acc[a][b][c] = 0.f;

    int ra = (lane & 7) + ((lane >> 3) & 1) * 8;
    int ca = ((lane >> 4) & 1) * 8;
    int rb = (lane & 7) + ((lane >> 4) & 1) * 8;
    int cb = ((lane >> 3) & 1) * 8;

    cp_wait<0>();
    __syncthreads();

    #pragma unroll
    for (int kk = 0; kk < K; kk += 16){
        uint32_t af[4][4], bf[4][2];
        #pragma unroll
        for (int mi=0; mi<4; mi++)
            ldsm_x4(af[mi], smaddr(&As[(wm + mi*16 + ra)*PAST + kk + ca]));
        #pragma unroll
        for (int p=0; p<2; p++){
            uint32_t r4[4];
            ldsm_x4(r4, smaddr(&Bs[(wn + p*16 + rb)*PAST + kk + cb]));
            bf[2*p  ][0] = r4[0]; bf[2*p  ][1] = r4[1];
            bf[2*p+1][0] = r4[2]; bf[2*p+1][1] = r4[3];
        }
        #pragma unroll
        for (int mi=0; mi<4; mi++)
            #pragma unroll
            for (int ni=0; ni<4; ni++)
                mma16(acc[mi][ni], af[mi], bf[ni]);
    }

    size_t cbase = bn0 + wn + tg*8;
    #pragma unroll
    for (int mi=0; mi<4; mi++){
        size_t r0 = bm0 + wm + mi*16 + g;
        uint4 v0, v1;
        __half2* p0 = (__half2*)&v0;
        __half2* p1 = (__half2*)&v1;
        #pragma unroll
        for (int ni=0; ni<4; ni++){
            p0[ni] = __floats2half2_rn(acc[mi][ni][0], acc[mi][ni][1]);
            p1[ni] = __floats2half2_rn(acc[mi][ni][2], acc[mi][ni][3]);
        }
        *(uint4*)(C + r0*N + cbase)     = v0;
        *(uint4*)(C + (r0+8)*N + cbase) = v1;
    }
}

// ---------------- fused h GEMM (fp16) + edge bucketing prologue ----------------
#define HAST 40
#define HBKT 32

__global__ __launch_bounds__(256) void k_hgemm(
    const float* __restrict__ ea, const float* __restrict__ W1, const float* __restrict__ b1,
    const float* __restrict__ b2, const int* __restrict__ ei)
{
    __shared__ __half As[BMt*HAST];
    __shared__ __half Bs[BMt*HAST];
    __shared__ float eas[BMt*EDIM];
    __shared__ float W1s[EDIM*KDIM];
    __shared__ float b1s[KDIM];
    int tid = threadIdx.x;

    // ---- bucket CSR build: 1024 blocks x 256 threads >= 65536 edges ----
    {
        int gtid = (blockIdx.y * gridDim.x + blockIdx.x) * 256 + tid;
        if (gtid < N_EDGES){
            int s = ei[gtid];
            int slot = atomicAdd(&g_deg[s], 1);
            g_csr[s*MAXDEG + slot] = gtid;
        }
    }

    int lane = tid & 31, warp = tid >> 5;
    int g = lane >> 2, tg = lane & 3;
    int wm = (warp >> 2) * 64;
    int wn = (warp & 3) * 32;
    size_t bm0 = (size_t)blockIdx.y * BMt;
    size_t bn0 = (size_t)blockIdx.x * BNt;

    for (int i = tid; i < BMt*EDIM; i += 256) eas[i] = ea[bm0*EDIM + i];
    for (int i = tid; i < EDIM*KDIM; i += 256) W1s[i] = W1[i];
    if (tid < KDIM) b1s[tid] = b1[tid];

    float acc[4][4][4];
    #pragma unroll
    for (int a=0;a<4;a++)
        #pragma unroll
        for (int b=0;b<4;b++)
            #pragma unroll
            for (int c=0;c<4;c++) acc[a][b][c] = 0.f;

    int ra = (lane & 7) + ((lane >> 3) & 1) * 8;
    int ca = ((lane >> 4) & 1) * 8;
    int rb = (lane & 7) + ((lane >> 4) & 1) * 8;
    int cb = ((lane >> 3) & 1) * 8;

    __syncthreads();

    for (int k0 = 0; k0 < KDIM; k0 += HBKT){
        #pragma unroll
        for (int i = tid; i < BMt*4; i += 256){
            int r = i >> 2, s = (i & 3) << 3;
            cp16(&Bs[r*HAST + s], g_W2T + (size_t)(bn0 + r)*KDIM + k0 + s);
        }
        cp_commit();
        {
            int c = tid & 31;
            int rg = tid >> 5;
            float w0 = W1s[0*KDIM + k0 + c], w1 = W1s[1*KDIM + k0 + c];
            float w2 = W1s[2*KDIM + k0 + c], w3 = W1s[3*KDIM + k0 + c];
            float w4 = W1s[4*KDIM + k0 + c], w5 = W1s[5*KDIM + k0 + c];
            float bb = b1s[k0 + c];
            #pragma unroll
            for (int i = 0; i < 16; i++){
                int r = rg*16 + i;
                const float* er = &eas[r*EDIM];
                float v = bb + er[0]*w0 + er[1]*w1 + er[2]*w2 + er[3]*w3 + er[4]*w4 + er[5]*w5;
                As[r*HAST + c] = __float2half_rn(gelu_f(v));
            }
        }
        cp_wait<0>();
        __syncthreads();
        #pragma unroll
        for (int kk = 0; kk < HBKT; kk += 16){
            uint32_t af[4][4], bf[4][2];
            #pragma unroll
            for (int mi=0; mi<4; mi++)
                ldsm_x4(af[mi], smaddr(&As[(wm + mi*16 + ra)*HAST + kk + ca]));
            #pragma unroll
            for (int p=0; p<2; p++){
                uint32_t r4[4];
                ldsm_x4(r4, smaddr(&Bs[(wn + p*16 + rb)*HAST + kk + cb]));
                bf[2*p  ][0] = r4[0]; bf[2*p  ][1] = r4[1];
                bf[2*p+1][0] = r4[2]; bf[2*p+1][1] = r4[3];
            }
            #pragma unroll
            for (int mi=0; mi<4; mi++)
                #pragma unroll
                for (int ni=0; ni<4; ni++)
                    mma16(acc[mi][ni], af[mi], bf[ni]);
        }
        __syncthreads();
    }

    size_t cbase = bn0 + wn + tg*8;
    #pragma unroll
    for (int mi=0; mi<4; mi++){
        size_t r0 = bm0 + wm + mi*16 + g;
        uint4 v0, v1;
        __half2* p0 = (__half2*)&v0;
        __half2* p1 = (__half2*)&v1;
        #pragma unroll
        for (int ni=0; ni<4; ni++){
            int cg = (int)bn0 + wn + ni*8 + (tg<<1);
            float bb0 = b2[cg], bb1 = b2[cg+1];
            p0[ni] = __floats2half2_rn(gelu_f(acc[mi][ni][0] + bb0), gelu_f(acc[mi][ni][1] + bb1));
            p1[ni] = __floats2half2_rn(gelu_f(acc[mi][ni][2] + bb0), gelu_f(acc[mi][ni][3] + bb1));
        }
        *(uint4*)(g_h + r0*KDIM + cbase)     = v0;
        *(uint4*)(g_h + (r0+8)*KDIM + cbase) = v1;
    }
}

// ---------------- fp16 edge stage: B fragments direct from gmem, h via cp.async smem ----------------
#define HST 264
#define EDGE_SMEM ((16*HST)*2 + LDIM*4 + MAXDEG*8)

__global__ __launch_bounds__(256) void k_edge(const int* __restrict__ ei,
                                              float* __restrict__ agg)
{
    extern __shared__ __half smh[];
    __half* hs   = smh;                          // [16][264]
    float*  xb3s = (float*)(hs + 16*HST);        // [64]
    int*    earr = (int*)(xb3s + LDIM);          // [128]
    int*    dsts = earr + MAXDEG;                // [128]

    int n = blockIdx.x;
    int deg = g_deg[n];
    if (deg == 0) return;

    int t = threadIdx.x;
    int lane = t & 31, warp = t >> 5;
    int g = lane >> 2, tg = lane & 3;
    int n0 = warp * 8;                           // this warp's 8 output cols (og = warp)

    // B fragments: 8 x LDG.128 per lane, coalesced, into registers (stay for all chunks)
    uint4 pf[8];
    {
        const uint4* Pf = (const uint4*)(g_P + (size_t)n * KL + (warp << 11)) + lane;
        #pragma unroll
        for (int p = 0; p < 8; p++) pf[p] = Pf[p << 5];   // +p*256 halves = +32 uint4
    }
    if (t < LDIM) xb3s[t] = g_xb3[n*LDIM + t];

    int ra  = (lane & 7) + ((lane >> 3) & 1) * 8;
    int ca  = ((lane >> 4) & 1) * 8;

    for (int i = t; i < deg; i += 256){
        int e = g_csr[n*MAXDEG + i];
        earr[i] = e;
        dsts[i] = ei[N_EDGES + e];
    }
    __syncthreads();
    int nch = (deg + 15) >> 4;

    for (int c = 0; c < nch; c++){
        int base = c*16;
        #pragma unroll
        for (int q = 0; q < 2; q++){
            int i = t + q*256;
            int slot = i >> 5, seg = i & 31;
            int eidx = base + slot; if (eidx >= deg) eidx = deg - 1;
            cp16(&hs[slot*HST + (seg<<3)], g_h + (size_t)earr[eidx]*KDIM + (seg<<3));
        }
        cp_commit();
        cp_wait<0>();
        __syncthreads();

        int csz = min(16, deg - base);
        float acc[4] = {0,0,0,0};
        #pragma unroll
        for (int kb = 0; kb < 16; kb++){
            uint32_t a[4];
            ldsm_x4(a, smaddr(&hs[ra*HST + kb*16 + ca]));
            uint32_t b[2];
            const uint32_t* pw = (const uint32_t*)&pf[kb >> 1];
            if (kb & 1){ b[0] = pw[2]; b[1] = pw[3]; }
            else       { b[0] = pw[0]; b[1] = pw[1]; }
            mma16(acc, a, b);
        }
        int cc = n0 + (tg<<1);
        float x0 = xb3s[cc], x1 = xb3s[cc+1];
        if (g < csz){
            int d = dsts[base + g];
            atomicAdd(&agg[(size_t)d*LDIM + cc    ], acc[0] + x0);
            atomicAdd(&agg[(size_t)d*LDIM + cc + 1], acc[1] + x1);
        }
        if (g + 8 < csz){
            int d = dsts[base + g + 8];
            atomicAdd(&agg[(size_t)d*LDIM + cc    ], acc[2] + x0);
            atomicAdd(&agg[(size_t)d*LDIM + cc + 1], acc[3] + x1);
        }
        __syncthreads();       // hs consumed before next chunk overwrite
    }
}

// ---------------- conv boundary: x1 = gelu(x@Wr + agg + bias), xh, xb3 = x1@B3 ----------------
__global__ __launch_bounds__(256) void k_boundary(
    const float* __restrict__ x, const float* __restrict__ Wr,
    const float* __restrict__ agg, const float* __restrict__ bias,
    const float* __restrict__ b3,
    float* __restrict__ x1, __half* __restrict__ xh, float* __restrict__ xb3)
{
    __shared__ float xs[4*LDIM];
    __shared__ float xs2[4*LDIM];
    int t = threadIdx.x;
    int o = t & 63, loc = t >> 6;
    int n0 = blockIdx.x * 4;
    xs[t] = x[(size_t)n0*LDIM + t];
    __syncthreads();
    int n = n0 + loc;
    float v = 0.f;
    #pragma unroll 8
    for (int i = 0; i < LDIM; i++) v += xs[loc*LDIM + i] * __ldg(&Wr[i*LDIM + o]);
    v += agg[(size_t)n*LDIM + o] + bias[o];
    v = gelu_f(v);
    x1[(size_t)n*LDIM + o] = v;
    xh[(size_t)n*LDIM + o] = __float2half_rn(v);
    xs2[t] = v;
    __syncthreads();
    float w = 0.f;
    #pragma unroll 8
    for (int i = 0; i < LDIM; i++) w += xs2[loc*LDIM + i] * __ldg(&b3[i*LDIM + o]);
    xb3[(size_t)n*LDIM + o] = w;
}

// ---------------- final node matmul: out = x @ Wr + agg + bias ----------------
__global__ __launch_bounds__(256) void k_final(
    const float* __restrict__ x, const float* __restrict__ Wr,
    const float* __restrict__ agg, const float* __restrict__ bias,
    float* __restrict__ out)
{
    __shared__ float xs[4*LDIM];
    int t = threadIdx.x;
    int o = t & 63, loc = t >> 6;
    int n0 = blockIdx.x * 4;
    xs[t] = x[(size_t)n0*LDIM + t];
    __syncthreads();
    int n = n0 + loc;
    float v = 0.f;
    #pragma unroll 8
    for (int i = 0; i < LDIM; i++) v += xs[loc*LDIM + i] * __ldg(&Wr[i*LDIM + o]);
    v += agg[(size_t)n*LDIM + o] + bias[o];
    out[(size_t)n*LDIM + o] = v;
}

// ---------------- launch ----------------
extern "C" void kernel_launch(void* const* d_in, const int* in_sizes, int n_in,
                              void* d_out, int out_size)
{
    const float* nodes = (const float*)d_in[0];
    const int*   ei    = (const int*)  d_in[1];
    const float* ea    = (const float*)d_in[2];
    const float* W1    = (const float*)d_in[3];
    const float* b1    = (const float*)d_in[4];
    const float* W2    = (const float*)d_in[5];
    const float* b2    = (const float*)d_in[6];
    const float* W3    = (const float*)d_in[7];
    const float* b3    = (const float*)d_in[8];
    const float* Wr    = (const float*)d_in[9];
    const float* bias  = (const float*)d_in[10];
    float* out = (float*)d_out;

    __half *pP, *pXh;
    float *pX1, *pXb3, *pAgg, *pAgg2;
    cudaGetSymbolAddress((void**)&pP,    g_P);
    cudaGetSymbolAddress((void**)&pXh,   g_xh);
    cudaGetSymbolAddress((void**)&pX1,   g_x1);
    cudaGetSymbolAddress((void**)&pXb3,  g_xb3);
    cudaGetSymbolAddress((void**)&pAgg,  g_agg);
    cudaGetSymbolAddress((void**)&pAgg2, g_agg2);

    static int smem_set = 0;
    if (!smem_set){
        cudaFuncSetAttribute(k_edge, cudaFuncAttributeMaxDynamicSharedMemorySize, EDGE_SMEM);
        smem_set = 1;
    }

    k_prep    <<<(KL*LDIM)/256, 256>>>(W3, W2, nodes, b3);                     // 0
    k_hgemm   <<<dim3(KDIM/BNt, N_EDGES/BMt), 256>>>(ea, W1, b1, b2, ei);      // 1 (+ CSR bucket)
    k_gemmP   <<<dim3(KL/BNt, N_NODES/BMt), 256>>>(pXh, pP);                   // 2 (conv1 P)
    k_edge    <<<N_NODES, 256, EDGE_SMEM>>>(ei, pAgg);                         // 3  <-- profiled
    k_boundary<<<N_NODES/4, 256>>>(nodes, Wr, pAgg, bias, b3, pX1, pXh, pXb3); // 4
    k_gemmP   <<<dim3(KL/BNt, N_NODES/BMt), 256>>>(pXh, pP);                   // 5 (conv2 P)
    k_edge    <<<N_NODES, 256, EDGE_SMEM>>>(ei, pAgg2);                        // 6
    k_final   <<<N_NODES/4, 256>>>(pX1, Wr, pAgg2, bias, out);                 // 7
}

// round 16
// speedup vs baseline: 1.0569x; 1.0437x over previous
#include <cuda_runtime.h>
#include <cuda_fp16.h>
#include <cstdint>

#define N_NODES 4096
#define N_EDGES 65536
#define LDIM 64
#define KDIM 256
#define EDIM 6
#define KL (KDIM*LDIM)   /* 16384 */
#define MAXDEG 128

// Layout notes: identical to R15 (g_h warp-tile-permuted; g_P in mma-B-fragment
// order with sigma baked into W3pT; k_edge loads B fragments straight from gmem).

// ---------------- scratch ----------------
__device__ __half g_W3pT[(size_t)KL*LDIM];
__device__ __half g_W2T[KDIM*KDIM];
__device__ __half g_xh[N_NODES*LDIM];
__device__ __half g_h [(size_t)N_EDGES*KDIM];
__device__ __half g_P [(size_t)N_NODES*KL];
__device__ float  g_x1 [N_NODES*LDIM];
__device__ float  g_xb3[N_NODES*LDIM];
__device__ float  g_agg [N_NODES*LDIM];
__device__ float  g_agg2[N_NODES*LDIM];
__device__ int    g_deg[N_NODES];
__device__ int    g_csr[N_NODES*MAXDEG];

// ---------------- helpers ----------------
__device__ __forceinline__ float gelu_f(float x){
    return 0.5f * x * (1.0f + erff(x * 0.70710678118654752440f));
}
__device__ __forceinline__ void mma16(float* c, const uint32_t* a, const uint32_t* b){
    asm volatile(
        "mma.sync.aligned.m16n8k16.row.col.f32.f16.f16.f32 "
        "{%0,%1,%2,%3}, {%4,%5,%6,%7}, {%8,%9}, {%0,%1,%2,%3};\n"
        : "+f"(c[0]), "+f"(c[1]), "+f"(c[2]), "+f"(c[3])
        : "r"(a[0]), "r"(a[1]), "r"(a[2]), "r"(a[3]), "r"(b[0]), "r"(b[1]));
}
__device__ __forceinline__ uint32_t smaddr(const void* p){
    return (uint32_t)__cvta_generic_to_shared(p);
}
__device__ __forceinline__ void ldsm_x4(uint32_t* r, uint32_t a){
    asm volatile("ldmatrix.sync.aligned.m8n8.x4.shared.b16 {%0,%1,%2,%3}, [%4];"
        : "=r"(r[0]), "=r"(r[1]), "=r"(r[2]), "=r"(r[3]) : "r"(a));
}
__device__ __forceinline__ void cp16(void* smem_dst, const void* gsrc){
    asm volatile("cp.async.cg.shared.global [%0], [%1], 16;\n"
                 :: "r"(smaddr(smem_dst)), "l"(gsrc));
}
__device__ __forceinline__ void cp_commit(){
    asm volatile("cp.async.commit_group;\n");
}
template<int N> __device__ __forceinline__ void cp_wait(){
    asm volatile("cp.async.wait_group %0;\n" :: "n"(N));
}
__device__ __forceinline__ int sigma32(int v){
    return (((v & 7) >> 1) << 3) + ((v >> 3) << 1) + (v & 1);
}

// ---------------- prep: W3pT (fragment+sigma order), W2T, xh, deg=0 ----------------
__global__ void k_prep(const float* __restrict__ W3, const float* __restrict__ W2,
                       const float* __restrict__ nodes){
    int idx = blockIdx.x*256 + threadIdx.x;        // 0 .. 1048575
    {
        int col = idx >> 6, i = idx & 63;
        int a = (col & ~31) | sigma32(col & 31);
        int og   = a >> 11;
        int rem  = a & 2047;
        int p    = rem >> 8;
        int rem2 = rem & 255;
        int lane = rem2 >> 3;
        int pos  = rem2 & 7;
        int no = lane >> 2, j = lane & 3;
        int w2 = pos >> 2,  pb = pos & 3;
        int kp   = ((pb >> 1) << 3) + (j << 1) + (pb & 1);
        int slot = ((p << 1) + w2) * 16 + kp;
        int k_log = (slot & ~31) | sigma32(slot & 31);
        int o = (og << 3) + no;
        g_W3pT[idx] = __float2half_rn(W3[k_log*(LDIM*LDIM) + i*LDIM + o]);
    }
    if (idx < KDIM*KDIM){
        int n = idx >> 8, k = idx & 255;
        g_W2T[idx] = __float2half_rn(W2[k*KDIM + n]);
    }
    if (idx < N_NODES*LDIM){
        g_xh[idx] = __float2half_rn(nodes[idx]);
    }
    if (idx < N_NODES) g_deg[idx] = 0;
}

// ---------------- shared bodies ----------------
#define BMt 128
#define BNt 128
#define PAST 72
#define HAST 40
#define HBKT 32
#define MEGA_SMEM (2*BMt*PAST*2)   /* 36864 B: max(gemmP 36864, hgemm 30720) */

__device__ __forceinline__ void gemmP_body(char* smb, int bx, int by,
    const __half* __restrict__ A, __half* __restrict__ C, int tid)
{
    __half* As = (__half*)smb;
    __half* Bs = (__half*)(smb + BMt*PAST*2);
    const int N = KL, K = LDIM;
    int lane = tid & 31, warp = tid >> 5;
    int g = lane >> 2, tg = lane & 3;
    int wm = (warp >> 2) * 64;
    int wn = (warp & 3) * 32;
    size_t bm0 = (size_t)by * BMt;
    size_t bn0 = (size_t)bx * BNt;

    #pragma unroll
    for (int i = tid; i < BMt*8; i += 256){
        int r = i >> 3, s = (i & 7) << 3;
        cp16(&As[r*PAST + s], A + (bm0 + r)*K + s);
    }
    #pragma unroll
    for (int i = tid; i < BNt*8; i += 256){
        int r = i >> 3, s = (i & 7) << 3;
        cp16(&Bs[r*PAST + s], g_W3pT + (size_t)(bn0 + r)*K + s);
    }
    cp_commit();

    float acc[4][4][4];
    #pragma unroll
    for (int a=0;a<4;a++)
        #pragma unroll
        for (int b=0;b<4;b++)
            #pragma unroll
            for (int c=0;c<4;c++) acc[a][b][c] = 0.f;

    int ra = (lane & 7) + ((lane >> 3) & 1) * 8;
    int ca = ((lane >> 4) & 1) * 8;
    int rb = (lane & 7) + ((lane >> 4) & 1) * 8;
    int cb = ((lane >> 3) & 1) * 8;

    cp_wait<0>();
    __syncthreads();

    #pragma unroll
    for (int kk = 0; kk < K; kk += 16){
        uint32_t af[4][4], bf[4][2];
        #pragma unroll
        for (int mi=0; mi<4; mi++)
            ldsm_x4(af[mi], smaddr(&As[(wm + mi*16 + ra)*PAST + kk + ca]));
        #pragma unroll
        for (int p=0; p<2; p++){
            uint32_t r4[4];
            ldsm_x4(r4, smaddr(&Bs[(wn + p*16 + rb)*PAST + kk + cb]));
            bf[2*p  ][0] = r4[0]; bf[2*p  ][1] = r4[1];
            bf[2*p+1][0] = r4[2]; bf[2*p+1][1] = r4[3];
        }
        #pragma unroll
        for (int mi=0; mi<4; mi++)
            #pragma unroll
            for (int ni=0; ni<4; ni++)
                mma16(acc[mi][ni], af[mi], bf[ni]);
    }

    size_t cbase = bn0 + wn + tg*8;
    #pragma unroll
    for (int mi=0; mi<4; mi++){
        size_t r0 = bm0 + wm + mi*16 + g;
        uint4 v0, v1;
        __half2* p0 = (__half2*)&v0;
        __half2* p1 = (__half2*)&v1;
        #pragma unroll
        for (int ni=0; ni<4; ni++){
            p0[ni] = __floats2half2_rn(acc[mi][ni][0], acc[mi][ni][1]);
            p1[ni] = __floats2half2_rn(acc[mi][ni][2], acc[mi][ni][3]);
        }
        *(uint4*)(C + r0*N + cbase)     = v0;
        *(uint4*)(C + (r0+8)*N + cbase) = v1;
    }
}

__device__ __forceinline__ void hgemm_body(char* smb, int bx, int by,
    const float* __restrict__ ea, const float* __restrict__ W1,
    const float* __restrict__ b1, const float* __restrict__ b2, int tid)
{
    __half* As  = (__half*)smb;                       // 10240 B
    __half* Bs  = (__half*)(smb + 10240);             // 10240 B
    float*  eas = (float*)(smb + 20480);              // 3072 B
    float*  W1s = (float*)(smb + 23552);              // 6144 B
    float*  b1s = (float*)(smb + 29696);              // 1024 B

    int lane = tid & 31, warp = tid >> 5;
    int g = lane >> 2, tg = lane & 3;
    int wm = (warp >> 2) * 64;
    int wn = (warp & 3) * 32;
    size_t bm0 = (size_t)by * BMt;
    size_t bn0 = (size_t)bx * BNt;

    for (int i = tid; i < BMt*EDIM; i += 256) eas[i] = ea[bm0*EDIM + i];
    for (int i = tid; i < EDIM*KDIM; i += 256) W1s[i] = W1[i];
    if (tid < KDIM) b1s[tid] = b1[tid];

    float acc[4][4][4];
    #pragma unroll
    for (int a=0;a<4;a++)
        #pragma unroll
        for (int b=0;b<4;b++)
            #pragma unroll
            for (int c=0;c<4;c++) acc[a][b][c] = 0.f;

    int ra = (lane & 7) + ((lane >> 3) & 1) * 8;
    int ca = ((lane >> 4) & 1) * 8;
    int rb = (lane & 7) + ((lane >> 4) & 1) * 8;
    int cb = ((lane >> 3) & 1) * 8;

    __syncthreads();

    for (int k0 = 0; k0 < KDIM; k0 += HBKT){
        #pragma unroll
        for (int i = tid; i < BMt*4; i += 256){
            int r = i >> 2, s = (i & 3) << 3;
            cp16(&Bs[r*HAST + s], g_W2T + (size_t)(bn0 + r)*KDIM + k0 + s);
        }
        cp_commit();
        {
            int c = tid & 31;
            int rg = tid >> 5;
            float w0 = W1s[0*KDIM + k0 + c], w1 = W1s[1*KDIM + k0 + c];
            float w2 = W1s[2*KDIM + k0 + c], w3 = W1s[3*KDIM + k0 + c];
            float w4 = W1s[4*KDIM + k0 + c], w5 = W1s[5*KDIM + k0 + c];
            float bb = b1s[k0 + c];
            #pragma unroll
            for (int i = 0; i < 16; i++){
                int r = rg*16 + i;
                const float* er = &eas[r*EDIM];
                float v = bb + er[0]*w0 + er[1]*w1 + er[2]*w2 + er[3]*w3 + er[4]*w4 + er[5]*w5;
                As[r*HAST + c] = __float2half_rn(gelu_f(v));
            }
        }
        cp_wait<0>();
        __syncthreads();
        #pragma unroll
        for (int kk = 0; kk < HBKT; kk += 16){
            uint32_t af[4][4], bf[4][2];
            #pragma unroll
            for (int mi=0; mi<4; mi++)
                ldsm_x4(af[mi], smaddr(&As[(wm + mi*16 + ra)*HAST + kk + ca]));
            #pragma unroll
            for (int p=0; p<2; p++){
                uint32_t r4[4];
                ldsm_x4(r4, smaddr(&Bs[(wn + p*16 + rb)*HAST + kk + cb]));
                bf[2*p  ][0] = r4[0]; bf[2*p  ][1] = r4[1];
                bf[2*p+1][0] = r4[2]; bf[2*p+1][1] = r4[3];
            }
            #pragma unroll
            for (int mi=0; mi<4; mi++)
                #pragma unroll
                for (int ni=0; ni<4; ni++)
                    mma16(acc[mi][ni], af[mi], bf[ni]);
        }
        __syncthreads();
    }

    size_t cbase = bn0 + wn + tg*8;
    #pragma unroll
    for (int mi=0; mi<4; mi++){
        size_t r0 = bm0 + wm + mi*16 + g;
        uint4 v0, v1;
        __half2* p0 = (__half2*)&v0;
        __half2* p1 = (__half2*)&v1;
        #pragma unroll
        for (int ni=0; ni<4; ni++){
            int cg = (int)bn0 + wn + ni*8 + (tg<<1);
            float bb0 = b2[cg], bb1 = b2[cg+1];
            p0[ni] = __floats2half2_rn(gelu_f(acc[mi][ni][0] + bb0), gelu_f(acc[mi][ni][1] + bb1));
            p1[ni] = __floats2half2_rn(gelu_f(acc[mi][ni][2] + bb0), gelu_f(acc[mi][ni][3] + bb1));
        }
        *(uint4*)(g_h + r0*KDIM + cbase)     = v0;
        *(uint4*)(g_h + (r0+8)*KDIM + cbase) = v1;
    }
}

// ---------------- mega1: hgemm(+bucket) U agg/xb3-init U gemmP(conv1) ----------------
// block ranges: [0,1024) hgemm, [1024,2048) init, [2048,6144) gemmP
__global__ __launch_bounds__(256, 2) void k_mega1(
    const float* __restrict__ ea, const float* __restrict__ W1,
    const float* __restrict__ b1, const float* __restrict__ b2,
    const int* __restrict__ ei,
    const __half* __restrict__ A, __half* __restrict__ C,
    const float* __restrict__ nodes, const float* __restrict__ b3)
{
    __shared__ __align__(16) char smb[MEGA_SMEM];
    int bid = blockIdx.x;
    int tid = threadIdx.x;

    if (bid < 1024){
        // bucket CSR build (1024 blocks x 256 >= 65536 edges)
        int gtid = bid*256 + tid;
        if (gtid < N_EDGES){
            int s = ei[gtid];
            int slot = atomicAdd(&g_deg[s], 1);
            g_csr[s*MAXDEG + slot] = gtid;
        }
        hgemm_body(smb, bid & 1, bid >> 1, ea, W1, b1, b2, tid);
    } else if (bid < 2048){
        int idx = (bid - 1024)*256 + tid;        // 0..262143
        g_agg[idx]  = 0.f;
        g_agg2[idx] = 0.f;
        int n = idx >> 6, o = idx & 63;
        const float* xr = nodes + n*LDIM;
        float v = 0.f;
        #pragma unroll 8
        for (int i = 0; i < LDIM; i++) v += xr[i] * __ldg(&b3[i*LDIM + o]);
        g_xb3[idx] = v;
    } else {
        int r = bid - 2048;                      // 0..4095
        gemmP_body(smb, r & 127, r >> 7, A, C, tid);
    }
}

// ---------------- standalone gemmP (conv 2) ----------------
__global__ __launch_bounds__(256, 3) void k_gemmP(
    const __half* __restrict__ A, __half* __restrict__ C)
{
    __shared__ __align__(16) char smb[MEGA_SMEM];
    gemmP_body(smb, blockIdx.x, blockIdx.y, A, C, threadIdx.x);
}

// ---------------- fp16 edge stage (unchanged from R15) ----------------
#define HST 264
#define EDGE_SMEM ((16*HST)*2 + LDIM*4 + MAXDEG*8)

__global__ __launch_bounds__(256) void k_edge(const int* __restrict__ ei,
                                              float* __restrict__ agg)
{
    extern __shared__ __half smh[];
    __half* hs   = smh;                          // [16][264]
    float*  xb3s = (float*)(hs + 16*HST);        // [64]
    int*    earr = (int*)(xb3s + LDIM);          // [128]
    int*    dsts = earr + MAXDEG;                // [128]

    int n = blockIdx.x;
    int deg = g_deg[n];
    if (deg == 0) return;

    int t = threadIdx.x;
    int lane = t & 31, warp = t >> 5;
    int g = lane >> 2, tg = lane & 3;
    int n0 = warp * 8;

    uint4 pf[8];
    {
        const uint4* Pf = (const uint4*)(g_P + (size_t)n * KL + (warp << 11)) + lane;
        #pragma unroll
        for (int p = 0; p < 8; p++) pf[p] = Pf[p << 5];
    }
    if (t < LDIM) xb3s[t] = g_xb3[n*LDIM + t];

    int ra  = (lane & 7) + ((lane >> 3) & 1) * 8;
    int ca  = ((lane >> 4) & 1) * 8;

    for (int i = t; i < deg; i += 256){
        int e = g_csr[n*MAXDEG + i];
        earr[i] = e;
        dsts[i] = ei[N_EDGES + e];
    }
    __syncthreads();
    int nch = (deg + 15) >> 4;

    for (int c = 0; c < nch; c++){
        int base = c*16;
        #pragma unroll
        for (int q = 0; q < 2; q++){
            int i = t + q*256;
            int slot = i >> 5, seg = i & 31;
            int eidx = base + slot; if (eidx >= deg) eidx = deg - 1;
            cp16(&hs[slot*HST + (seg<<3)], g_h + (size_t)earr[eidx]*KDIM + (seg<<3));
        }
        cp_commit();
        cp_wait<0>();
        __syncthreads();

        int csz = min(16, deg - base);
        float acc[4] = {0,0,0,0};
        #pragma unroll
        for (int kb = 0; kb < 16; kb++){
            uint32_t a[4];
            ldsm_x4(a, smaddr(&hs[ra*HST + kb*16 + ca]));
            uint32_t b[2];
            const uint32_t* pw = (const uint32_t*)&pf[kb >> 1];
            if (kb & 1){ b[0] = pw[2]; b[1] = pw[3]; }
            else       { b[0] = pw[0]; b[1] = pw[1]; }
            mma16(acc, a, b);
        }
        int cc = n0 + (tg<<1);
        float x0 = xb3s[cc], x1 = xb3s[cc+1];
        if (g < csz){
            int d = dsts[base + g];
            atomicAdd(&agg[(size_t)d*LDIM + cc    ], acc[0] + x0);
            atomicAdd(&agg[(size_t)d*LDIM + cc + 1], acc[1] + x1);
        }
        if (g + 8 < csz){
            int d = dsts[base + g + 8];
            atomicAdd(&agg[(size_t)d*LDIM + cc    ], acc[2] + x0);
            atomicAdd(&agg[(size_t)d*LDIM + cc + 1], acc[3] + x1);
        }
        __syncthreads();
    }
}

// ---------------- conv boundary: x1 = gelu(x@Wr + agg + bias), xh, xb3 = x1@B3 ----------------
__global__ __launch_bounds__(256) void k_boundary(
    const float* __restrict__ x, const float* __restrict__ Wr,
    const float* __restrict__ agg, const float* __restrict__ bias,
    const float* __restrict__ b3,
    float* __restrict__ x1, __half* __restrict__ xh, float* __restrict__ xb3)
{
    __shared__ float xs[4*LDIM];
    __shared__ float xs2[4*LDIM];
    int t = threadIdx.x;
    int o = t & 63, loc = t >> 6;
    int n0 = blockIdx.x * 4;
    xs[t] = x[(size_t)n0*LDIM + t];
    __syncthreads();
    int n = n0 + loc;
    float v = 0.f;
    #pragma unroll 8
    for (int i = 0; i < LDIM; i++) v += xs[loc*LDIM + i] * __ldg(&Wr[i*LDIM + o]);
    v += agg[(size_t)n*LDIM + o] + bias[o];
    v = gelu_f(v);
    x1[(size_t)n*LDIM + o] = v;
    xh[(size_t)n*LDIM + o] = __float2half_rn(v);
    xs2[t] = v;
    __syncthreads();
    float w = 0.f;
    #pragma unroll 8
    for (int i = 0; i < LDIM; i++) w += xs2[loc*LDIM + i] * __ldg(&b3[i*LDIM + o]);
    xb3[(size_t)n*LDIM + o] = w;
}

// ---------------- final node matmul: out = x @ Wr + agg + bias ----------------
__global__ __launch_bounds__(256) void k_final(
    const float* __restrict__ x, const float* __restrict__ Wr,
    const float* __restrict__ agg, const float* __restrict__ bias,
    float* __restrict__ out)
{
    __shared__ float xs[4*LDIM];
    int t = threadIdx.x;
    int o = t & 63, loc = t >> 6;
    int n0 = blockIdx.x * 4;
    xs[t] = x[(size_t)n0*LDIM + t];
    __syncthreads();
    int n = n0 + loc;
    float v = 0.f;
    #pragma unroll 8
    for (int i = 0; i < LDIM; i++) v += xs[loc*LDIM + i] * __ldg(&Wr[i*LDIM + o]);
    v += agg[(size_t)n*LDIM + o] + bias[o];
    out[(size_t)n*LDIM + o] = v;
}

// ---------------- launch ----------------
extern "C" void kernel_launch(void* const* d_in, const int* in_sizes, int n_in,
                              void* d_out, int out_size)
{
    const float* nodes = (const float*)d_in[0];
    const int*   ei    = (const int*)  d_in[1];
    const float* ea    = (const float*)d_in[2];
    const float* W1    = (const float*)d_in[3];
    const float* b1    = (const float*)d_in[4];
    const float* W2    = (const float*)d_in[5];
    const float* b2    = (const float*)d_in[6];
    const float* W3    = (const float*)d_in[7];
    const float* b3    = (const float*)d_in[8];
    const float* Wr    = (const float*)d_in[9];
    const float* bias  = (const float*)d_in[10];
    float* out = (float*)d_out;

    __half *pP, *pXh;
    float *pX1, *pXb3, *pAgg, *pAgg2;
    cudaGetSymbolAddress((void**)&pP,    g_P);
    cudaGetSymbolAddress((void**)&pXh,   g_xh);
    cudaGetSymbolAddress((void**)&pX1,   g_x1);
    cudaGetSymbolAddress((void**)&pXb3,  g_xb3);
    cudaGetSymbolAddress((void**)&pAgg,  g_agg);
    cudaGetSymbolAddress((void**)&pAgg2, g_agg2);

    static int smem_set = 0;
    if (!smem_set){
        cudaFuncSetAttribute(k_edge, cudaFuncAttributeMaxDynamicSharedMemorySize, EDGE_SMEM);
        smem_set = 1;
    }

    k_prep    <<<(KL*LDIM)/256, 256>>>(W3, W2, nodes);                         // 0
    k_mega1   <<<6144, 256>>>(ea, W1, b1, b2, ei, pXh, pP, nodes, b3);         // 1
    k_edge    <<<N_NODES, 256, EDGE_SMEM>>>(ei, pAgg);                         // 2
    k_boundary<<<N_NODES/4, 256>>>(nodes, Wr, pAgg, bias, b3, pX1, pXh, pXb3); // 3 <- profiled
    k_gemmP   <<<dim3(KL/BNt, N_NODES/BMt), 256>>>(pXh, pP);                   // 4 (conv2 P)
    k_edge    <<<N_NODES, 256, EDGE_SMEM>>>(ei, pAgg2);                        // 5
    k_final   <<<N_NODES/4, 256>>>(pX1, Wr, pAgg2, bias, out);                 // 6
}